// round 11
// baseline (speedup 1.0000x reference)
#include <cuda_runtime.h>
#include <math.h>

#define B   2
#define L   2048
#define HID 1024
#define NH  16
#define E   128
#define HS  64
#define ML  (B*L)          // 4096
#define KD  1024           // inner dim of projections

// ---------------- scratch (static device globals; no allocs allowed) -------
__device__ float g_q[B*NH*L*E];     // (b,h,l,e)   32 MB
__device__ float g_k[B*NH*L*E];     // (b,h,l,e)   32 MB
__device__ float g_v[B*NH*L*HS];    // (b,h,l,d)   16 MB
__device__ float g_gu1[B*NH*L];     // gate_u_1 per (b,h,l)

// ============================================================================
// Projection GEMM: C(ML x N) = A(ML x 1024) @ W^T(N x 1024) (+ bias)
// Output scattered into (B,NH,L,EG) layout.  tgt: 0->g_q, 1->g_k, 2->g_v
// 64x64 block tile, BK=16, 256 threads, 4x4 microtile.
// ============================================================================
__global__ __launch_bounds__(256) void proj_kernel(
    const float* __restrict__ A,
    const float* __restrict__ W,
    const float* __restrict__ bias,   // may be null
    int EG, int tgt)
{
    __shared__ float As[16][68];   // [k][m]
    __shared__ float Ws[16][68];   // [k][n]

    const int tid = threadIdx.x;
    const int tx  = tid & 15;      // n micro
    const int ty  = tid >> 4;      // m micro
    const int m0  = blockIdx.y * 64;
    const int n0  = blockIdx.x * 64;

    const int lrow = tid >> 2;         // 0..63
    const int lkq  = (tid & 3) * 4;    // 0,4,8,12

    const float* Aptr = A + (size_t)(m0 + lrow) * KD + lkq;
    const float* Wptr = W + (size_t)(n0 + lrow) * KD + lkq;

    float c[4][4];
    #pragma unroll
    for (int i = 0; i < 4; i++)
        #pragma unroll
        for (int j = 0; j < 4; j++) c[i][j] = 0.f;

    for (int k0 = 0; k0 < KD; k0 += 16) {
        float4 a4 = *(const float4*)(Aptr + k0);
        float4 w4 = *(const float4*)(Wptr + k0);
        As[lkq+0][lrow] = a4.x; As[lkq+1][lrow] = a4.y;
        As[lkq+2][lrow] = a4.z; As[lkq+3][lrow] = a4.w;
        Ws[lkq+0][lrow] = w4.x; Ws[lkq+1][lrow] = w4.y;
        Ws[lkq+2][lrow] = w4.z; Ws[lkq+3][lrow] = w4.w;
        __syncthreads();

        #pragma unroll
        for (int kk = 0; kk < 16; kk++) {
            float4 av = *(const float4*)&As[kk][ty*4];
            float4 wv = *(const float4*)&Ws[kk][tx*4];
            const float* af = (const float*)&av;
            const float* wf = (const float*)&wv;
            #pragma unroll
            for (int i = 0; i < 4; i++)
                #pragma unroll
                for (int j = 0; j < 4; j++)
                    c[i][j] = fmaf(af[i], wf[j], c[i][j]);
        }
        __syncthreads();
    }

    float* out = (tgt == 0) ? g_q : (tgt == 1) ? g_k : g_v;

    #pragma unroll
    for (int i = 0; i < 4; i++) {
        const int mm = m0 + ty*4 + i;
        const int bb = mm / L;
        const int ll = mm % L;
        #pragma unroll
        for (int j = 0; j < 4; j++) {
            const int nn = n0 + tx*4 + j;
            const int h  = nn / EG;
            const int e  = nn % EG;
            float v = c[i][j];
            if (bias) v += bias[nn];
            out[(((size_t)bb*NH + h)*L + ll)*EG + e] = v;
        }
    }
}

// ============================================================================
// Gate: one warp per (b,h,l).
// g = sigmoid((q @ Wg^T + bg).reshape(...,2,4).sum(-1))
// gu1 = gu*(gr*eco - 1) + 2
// ============================================================================
__global__ __launch_bounds__(256) void gate_kernel(
    const float* __restrict__ Wg,   // (8,128)
    const float* __restrict__ bg,   // (8)
    const float* __restrict__ eco)  // (NH)
{
    const int gw   = (blockIdx.x * blockDim.x + threadIdx.x) >> 5;
    const int lane = threadIdx.x & 31;
    if (gw >= B*NH*L) return;

    const float* qrow = g_q + (size_t)gw * E;
    float qv[4];
    #pragma unroll
    for (int i = 0; i < 4; i++) qv[i] = qrow[lane + 32*i];

    float d[8];
    #pragma unroll
    for (int j = 0; j < 8; j++) {
        float s = 0.f;
        #pragma unroll
        for (int i = 0; i < 4; i++)
            s = fmaf(qv[i], __ldg(&Wg[j*E + lane + 32*i]), s);
        #pragma unroll
        for (int off = 16; off; off >>= 1)
            s += __shfl_xor_sync(0xffffffffu, s, off);
        d[j] = s;
    }
    if (lane == 0) {
        float su = d[0]+d[1]+d[2]+d[3] + bg[0]+bg[1]+bg[2]+bg[3];
        float sr = d[4]+d[5]+d[6]+d[7] + bg[4]+bg[5]+bg[6]+bg[7];
        float gu = 1.f / (1.f + expf(-su));
        float gr = 1.f / (1.f + expf(-sr));
        const int h = (gw / L) % NH;
        g_gu1[gw] = fmaf(gu, fmaf(gr, eco[h], -1.f), 2.f);
    }
}

// ============================================================================
// Flash attention with gated rel_pos bias.
// Block = (qtile, h, b). BM=BN=64, 256 threads, 4x4 microtiles.
// ============================================================================
#define BM 64
#define BN 64
#define QSTR 132   // E + 4 pad
#define VSTR 68    // HS + 4 pad
#define PSTR 68    // BN + 4 pad

__device__ __forceinline__ float dot4(float4 a, float4 b, float c) {
    return fmaf(a.x, b.x, fmaf(a.y, b.y, fmaf(a.z, b.z, fmaf(a.w, b.w, c))));
}

__global__ __launch_bounds__(256, 2) void attn_kernel(
    const float* __restrict__ mask,     // (B, L)
    const float* __restrict__ relpos,   // (NH, L, L)
    float* __restrict__ out)            // (B, L, HID)
{
    extern __shared__ float sm[];
    float* Qs  = sm;                    // [BM][QSTR]
    float* Ks  = Qs  + BM*QSTR;         // [BN][QSTR]
    float* Vs  = Ks  + BN*QSTR;         // [BN][VSTR]
    float* Ps  = Vs  + BN*VSTR;         // [BM][PSTR]  (P row-major)
    float* gur = Ps  + BM*PSTR;         // [BM]

    const int tid = threadIdx.x;
    const int tx  = tid & 15;
    const int ty  = tid >> 4;
    const int r0  = ty * 4;      // local query rows
    const int c0  = tx * 4;      // local key cols / out dims

    const int qt = blockIdx.x;
    const int h  = blockIdx.y;
    const int b  = blockIdx.z;
    const int lq0 = qt * BM;

    const size_t bh = (size_t)b*NH + h;
    const float* Qg = g_q + (bh*L + lq0) * E;
    const float* Kg = g_k + bh*L*E;
    const float* Vg = g_v + bh*L*HS;
    const float* relp = relpos + ((size_t)h*L + lq0) * L;

    // Q tile load (64x128 -> 2048 float4)
    for (int t = tid; t < BM*(E/4); t += 256) {
        const int r  = t >> 5;         // /32
        const int e4 = t & 31;
        *(float4*)(Qs + r*QSTR + e4*4) = *(const float4*)(Qg + r*E + e4*4);
    }
    if (tid < BM) gur[tid] = g_gu1[bh*L + lq0 + tid];

    float m_i[4], l_i[4], acc[4][4];
    #pragma unroll
    for (int i = 0; i < 4; i++) {
        m_i[i] = -1e30f; l_i[i] = 0.f;
        #pragma unroll
        for (int j = 0; j < 4; j++) acc[i][j] = 0.f;
    }

    for (int kt = 0; kt < L/BN; kt++) {
        const int kc0 = kt * BN;
        __syncthreads();   // prev PV / Q stores done before K,V overwrite

        for (int t = tid; t < BN*(E/4); t += 256) {
            const int r  = t >> 5;
            const int e4 = t & 31;
            *(float4*)(Ks + r*QSTR + e4*4) =
                *(const float4*)(Kg + (size_t)(kc0 + r)*E + e4*4);
        }
        for (int t = tid; t < BN*(HS/4); t += 256) {
            const int r  = t >> 4;
            const int d4 = t & 15;
            *(float4*)(Vs + r*VSTR + d4*4) =
                *(const float4*)(Vg + (size_t)(kc0 + r)*HS + d4*4);
        }
        __syncthreads();

        // ---- S = Q K^T ----
        float s[4][4];
        #pragma unroll
        for (int i = 0; i < 4; i++)
            #pragma unroll
            for (int j = 0; j < 4; j++) s[i][j] = 0.f;

        #pragma unroll 8
        for (int e4 = 0; e4 < 32; e4++) {
            float4 a[4], k4[4];
            #pragma unroll
            for (int i = 0; i < 4; i++)
                a[i]  = *(const float4*)(Qs + (r0+i)*QSTR + e4*4);
            #pragma unroll
            for (int j = 0; j < 4; j++)
                k4[j] = *(const float4*)(Ks + (c0+j)*QSTR + e4*4);
            #pragma unroll
            for (int i = 0; i < 4; i++)
                #pragma unroll
                for (int j = 0; j < 4; j++)
                    s[i][j] = dot4(a[i], k4[j], s[i][j]);
        }

        // ---- scale + mask + gated rel_pos ----
        const float4 mk = *(const float4*)(mask + (size_t)b*L + kc0 + c0);
        const float* mkf = (const float*)&mk;
        #pragma unroll
        for (int i = 0; i < 4; i++) {
            const float gi = gur[r0 + i];
            const float4 rp = *(const float4*)(relp + (size_t)(r0+i)*L + kc0 + c0);
            const float* rpf = (const float*)&rp;
            #pragma unroll
            for (int j = 0; j < 4; j++)
                s[i][j] = fmaf(s[i][j], 0.125f, mkf[j] + gi * rpf[j]);
        }

        // ---- online softmax (reduce over 16-lane row groups) ----
        #pragma unroll
        for (int i = 0; i < 4; i++) {
            float mt = fmaxf(fmaxf(s[i][0], s[i][1]), fmaxf(s[i][2], s[i][3]));
            #pragma unroll
            for (int off = 1; off < 16; off <<= 1)
                mt = fmaxf(mt, __shfl_xor_sync(0xffffffffu, mt, off));
            const float mnew = fmaxf(m_i[i], mt);
            const float corr = __expf(m_i[i] - mnew);
            m_i[i] = mnew;
            float rs = 0.f;
            #pragma unroll
            for (int j = 0; j < 4; j++) {
                s[i][j] = __expf(s[i][j] - mnew);
                rs += s[i][j];
            }
            #pragma unroll
            for (int off = 1; off < 16; off <<= 1)
                rs += __shfl_xor_sync(0xffffffffu, rs, off);
            l_i[i] = l_i[i] * corr + rs;
            #pragma unroll
            for (int j = 0; j < 4; j++) {
                acc[i][j] *= corr;
                Ps[(r0+i)*PSTR + c0 + j] = s[i][j];
            }
        }
        __syncthreads();

        // ---- acc += P @ V ----
        #pragma unroll 4
        for (int c4 = 0; c4 < 16; c4++) {
            float4 p4[4];
            #pragma unroll
            for (int i = 0; i < 4; i++)
                p4[i] = *(const float4*)(Ps + (r0+i)*PSTR + c4*4);
            #pragma unroll
            for (int cc = 0; cc < 4; cc++) {
                const float4 vv = *(const float4*)(Vs + (c4*4+cc)*VSTR + c0);
                const float* vf = (const float*)&vv;
                #pragma unroll
                for (int i = 0; i < 4; i++) {
                    const float p = ((const float*)&p4[i])[cc];
                    #pragma unroll
                    for (int j = 0; j < 4; j++)
                        acc[i][j] = fmaf(p, vf[j], acc[i][j]);
                }
            }
        }
    }

    // ---- epilogue ----
    #pragma unroll
    for (int i = 0; i < 4; i++) {
        const float inv = 1.f / l_i[i];
        float4 o;
        o.x = acc[i][0]*inv; o.y = acc[i][1]*inv;
        o.z = acc[i][2]*inv; o.w = acc[i][3]*inv;
        *(float4*)(out + ((size_t)b*L + lq0 + r0 + i)*HID + h*HS + c0) = o;
    }
}

// ============================================================================
extern "C" void kernel_launch(void* const* d_in, const int* in_sizes, int n_in,
                              void* d_out, int out_size) {
    const float* hs   = (const float*)d_in[0];
    const float* mask = (const float*)d_in[1];
    const float* rel  = (const float*)d_in[2];
    const float* Wq   = (const float*)d_in[3];
    const float* bq   = (const float*)d_in[4];
    const float* Wk   = (const float*)d_in[5];
    const float* Wv   = (const float*)d_in[6];
    const float* bv   = (const float*)d_in[7];
    const float* Wg   = (const float*)d_in[8];
    const float* bg   = (const float*)d_in[9];
    const float* eco  = (const float*)d_in[10];
    float* out = (float*)d_out;

    // projections: Q (N=2048, bias), K (N=2048, no bias), V (N=1024, bias)
    proj_kernel<<<dim3(2048/64, ML/64), 256>>>(hs, Wq, bq,  E,  0);
    proj_kernel<<<dim3(2048/64, ML/64), 256>>>(hs, Wk, nullptr, E, 1);
    proj_kernel<<<dim3(1024/64, ML/64), 256>>>(hs, Wv, bv,  HS, 2);

    // gates
    gate_kernel<<<(B*NH*L)/8, 256>>>(Wg, bg, eco);

    // attention
    const int smem_bytes = (BM*QSTR + BN*QSTR + BN*VSTR + BM*PSTR + BM) * sizeof(float);
    cudaFuncSetAttribute(attn_kernel,
                         cudaFuncAttributeMaxDynamicSharedMemorySize, smem_bytes);
    attn_kernel<<<dim3(L/BM, NH, B), 256, smem_bytes>>>(mask, rel, out);
}

// round 12
// speedup vs baseline: 1.0007x; 1.0007x over previous
#include <cuda_runtime.h>
#include <math.h>

#define B   2
#define L   2048
#define HID 1024
#define NH  16
#define E   128
#define HS  64
#define ML  (B*L)          // 4096
#define KD  1024           // inner dim of projections

// ---------------- scratch (static device globals; no allocs allowed) -------
__device__ float g_q[B*NH*L*E];     // (b,h,l,e)   32 MB
__device__ float g_k[B*NH*L*E];     // (b,h,l,e)   32 MB
__device__ float g_v[B*NH*L*HS];    // (b,h,l,d)   16 MB
__device__ float g_gu1[B*NH*L];     // gate_u_1 per (b,h,l)

// ============================================================================
// Projection GEMM: C(ML x N) = A(ML x 1024) @ W^T(N x 1024) (+ bias)
// Output scattered into (B,NH,L,EG) layout.  tgt: 0->g_q, 1->g_k, 2->g_v
// 64x64 block tile, BK=16, 256 threads, 4x4 microtile.
// ============================================================================
__global__ __launch_bounds__(256) void proj_kernel(
    const float* __restrict__ A,
    const float* __restrict__ W,
    const float* __restrict__ bias,   // may be null
    int EG, int tgt)
{
    __shared__ float As[16][68];   // [k][m]
    __shared__ float Ws[16][68];   // [k][n]

    const int tid = threadIdx.x;
    const int tx  = tid & 15;      // n micro
    const int ty  = tid >> 4;      // m micro
    const int m0  = blockIdx.y * 64;
    const int n0  = blockIdx.x * 64;

    const int lrow = tid >> 2;         // 0..63
    const int lkq  = (tid & 3) * 4;    // 0,4,8,12

    const float* Aptr = A + (size_t)(m0 + lrow) * KD + lkq;
    const float* Wptr = W + (size_t)(n0 + lrow) * KD + lkq;

    float c[4][4];
    #pragma unroll
    for (int i = 0; i < 4; i++)
        #pragma unroll
        for (int j = 0; j < 4; j++) c[i][j] = 0.f;

    for (int k0 = 0; k0 < KD; k0 += 16) {
        float4 a4 = *(const float4*)(Aptr + k0);
        float4 w4 = *(const float4*)(Wptr + k0);
        As[lkq+0][lrow] = a4.x; As[lkq+1][lrow] = a4.y;
        As[lkq+2][lrow] = a4.z; As[lkq+3][lrow] = a4.w;
        Ws[lkq+0][lrow] = w4.x; Ws[lkq+1][lrow] = w4.y;
        Ws[lkq+2][lrow] = w4.z; Ws[lkq+3][lrow] = w4.w;
        __syncthreads();

        #pragma unroll
        for (int kk = 0; kk < 16; kk++) {
            float4 av = *(const float4*)&As[kk][ty*4];
            float4 wv = *(const float4*)&Ws[kk][tx*4];
            const float* af = (const float*)&av;
            const float* wf = (const float*)&wv;
            #pragma unroll
            for (int i = 0; i < 4; i++)
                #pragma unroll
                for (int j = 0; j < 4; j++)
                    c[i][j] = fmaf(af[i], wf[j], c[i][j]);
        }
        __syncthreads();
    }

    float* out = (tgt == 0) ? g_q : (tgt == 1) ? g_k : g_v;

    #pragma unroll
    for (int i = 0; i < 4; i++) {
        const int mm = m0 + ty*4 + i;
        const int bb = mm / L;
        const int ll = mm % L;
        #pragma unroll
        for (int j = 0; j < 4; j++) {
            const int nn = n0 + tx*4 + j;
            const int h  = nn / EG;
            const int e  = nn % EG;
            float v = c[i][j];
            if (bias) v += bias[nn];
            out[(((size_t)bb*NH + h)*L + ll)*EG + e] = v;
        }
    }
}

// ============================================================================
// Gate: one warp per (b,h,l).
// g = sigmoid((q @ Wg^T + bg).reshape(...,2,4).sum(-1))
// gu1 = gu*(gr*eco - 1) + 2
// ============================================================================
__global__ __launch_bounds__(256) void gate_kernel(
    const float* __restrict__ Wg,   // (8,128)
    const float* __restrict__ bg,   // (8)
    const float* __restrict__ eco)  // (NH)
{
    const int gw   = (blockIdx.x * blockDim.x + threadIdx.x) >> 5;
    const int lane = threadIdx.x & 31;
    if (gw >= B*NH*L) return;

    const float* qrow = g_q + (size_t)gw * E;
    float qv[4];
    #pragma unroll
    for (int i = 0; i < 4; i++) qv[i] = qrow[lane + 32*i];

    float d[8];
    #pragma unroll
    for (int j = 0; j < 8; j++) {
        float s = 0.f;
        #pragma unroll
        for (int i = 0; i < 4; i++)
            s = fmaf(qv[i], __ldg(&Wg[j*E + lane + 32*i]), s);
        #pragma unroll
        for (int off = 16; off; off >>= 1)
            s += __shfl_xor_sync(0xffffffffu, s, off);
        d[j] = s;
    }
    if (lane == 0) {
        float su = d[0]+d[1]+d[2]+d[3] + bg[0]+bg[1]+bg[2]+bg[3];
        float sr = d[4]+d[5]+d[6]+d[7] + bg[4]+bg[5]+bg[6]+bg[7];
        float gu = 1.f / (1.f + expf(-su));
        float gr = 1.f / (1.f + expf(-sr));
        const int h = (gw / L) % NH;
        g_gu1[gw] = fmaf(gu, fmaf(gr, eco[h], -1.f), 2.f);
    }
}

// ============================================================================
// Flash attention with gated rel_pos bias.
// Block = (qtile, h, b). BM=BN=64, 256 threads, 4x4 microtiles.
// ============================================================================
#define BM 64
#define BN 64
#define QSTR 132   // E + 4 pad
#define VSTR 68    // HS + 4 pad
#define PSTR 68    // BN + 4 pad

__device__ __forceinline__ float dot4(float4 a, float4 b, float c) {
    return fmaf(a.x, b.x, fmaf(a.y, b.y, fmaf(a.z, b.z, fmaf(a.w, b.w, c))));
}

__global__ __launch_bounds__(256, 2) void attn_kernel(
    const float* __restrict__ mask,     // (B, L)
    const float* __restrict__ relpos,   // (NH, L, L)
    float* __restrict__ out)            // (B, L, HID)
{
    extern __shared__ float sm[];
    float* Qs  = sm;                    // [BM][QSTR]
    float* Ks  = Qs  + BM*QSTR;         // [BN][QSTR]
    float* Vs  = Ks  + BN*QSTR;         // [BN][VSTR]
    float* Ps  = Vs  + BN*VSTR;         // [BM][PSTR]  (P row-major)
    float* gur = Ps  + BM*PSTR;         // [BM]

    const int tid = threadIdx.x;
    const int tx  = tid & 15;
    const int ty  = tid >> 4;
    const int r0  = ty * 4;      // local query rows
    const int c0  = tx * 4;      // local key cols / out dims

    const int qt = blockIdx.x;
    const int h  = blockIdx.y;
    const int b  = blockIdx.z;
    const int lq0 = qt * BM;

    const size_t bh = (size_t)b*NH + h;
    const float* Qg = g_q + (bh*L + lq0) * E;
    const float* Kg = g_k + bh*L*E;
    const float* Vg = g_v + bh*L*HS;
    const float* relp = relpos + ((size_t)h*L + lq0) * L;

    // Q tile load (64x128 -> 2048 float4)
    for (int t = tid; t < BM*(E/4); t += 256) {
        const int r  = t >> 5;         // /32
        const int e4 = t & 31;
        *(float4*)(Qs + r*QSTR + e4*4) = *(const float4*)(Qg + r*E + e4*4);
    }
    if (tid < BM) gur[tid] = g_gu1[bh*L + lq0 + tid];

    float m_i[4], l_i[4], acc[4][4];
    #pragma unroll
    for (int i = 0; i < 4; i++) {
        m_i[i] = -1e30f; l_i[i] = 0.f;
        #pragma unroll
        for (int j = 0; j < 4; j++) acc[i][j] = 0.f;
    }

    for (int kt = 0; kt < L/BN; kt++) {
        const int kc0 = kt * BN;
        __syncthreads();   // prev PV / Q stores done before K,V overwrite

        for (int t = tid; t < BN*(E/4); t += 256) {
            const int r  = t >> 5;
            const int e4 = t & 31;
            *(float4*)(Ks + r*QSTR + e4*4) =
                *(const float4*)(Kg + (size_t)(kc0 + r)*E + e4*4);
        }
        for (int t = tid; t < BN*(HS/4); t += 256) {
            const int r  = t >> 4;
            const int d4 = t & 15;
            *(float4*)(Vs + r*VSTR + d4*4) =
                *(const float4*)(Vg + (size_t)(kc0 + r)*HS + d4*4);
        }
        __syncthreads();

        // ---- S = Q K^T ----
        float s[4][4];
        #pragma unroll
        for (int i = 0; i < 4; i++)
            #pragma unroll
            for (int j = 0; j < 4; j++) s[i][j] = 0.f;

        #pragma unroll 8
        for (int e4 = 0; e4 < 32; e4++) {
            float4 a[4], k4[4];
            #pragma unroll
            for (int i = 0; i < 4; i++)
                a[i]  = *(const float4*)(Qs + (r0+i)*QSTR + e4*4);
            #pragma unroll
            for (int j = 0; j < 4; j++)
                k4[j] = *(const float4*)(Ks + (c0+j)*QSTR + e4*4);
            #pragma unroll
            for (int i = 0; i < 4; i++)
                #pragma unroll
                for (int j = 0; j < 4; j++)
                    s[i][j] = dot4(a[i], k4[j], s[i][j]);
        }

        // ---- scale + mask + gated rel_pos ----
        const float4 mk = *(const float4*)(mask + (size_t)b*L + kc0 + c0);
        const float* mkf = (const float*)&mk;
        #pragma unroll
        for (int i = 0; i < 4; i++) {
            const float gi = gur[r0 + i];
            const float4 rp = *(const float4*)(relp + (size_t)(r0+i)*L + kc0 + c0);
            const float* rpf = (const float*)&rp;
            #pragma unroll
            for (int j = 0; j < 4; j++)
                s[i][j] = fmaf(s[i][j], 0.125f, mkf[j] + gi * rpf[j]);
        }

        // ---- online softmax (reduce over 16-lane row groups) ----
        #pragma unroll
        for (int i = 0; i < 4; i++) {
            float mt = fmaxf(fmaxf(s[i][0], s[i][1]), fmaxf(s[i][2], s[i][3]));
            #pragma unroll
            for (int off = 1; off < 16; off <<= 1)
                mt = fmaxf(mt, __shfl_xor_sync(0xffffffffu, mt, off));
            const float mnew = fmaxf(m_i[i], mt);
            const float corr = __expf(m_i[i] - mnew);
            m_i[i] = mnew;
            float rs = 0.f;
            #pragma unroll
            for (int j = 0; j < 4; j++) {
                s[i][j] = __expf(s[i][j] - mnew);
                rs += s[i][j];
            }
            #pragma unroll
            for (int off = 1; off < 16; off <<= 1)
                rs += __shfl_xor_sync(0xffffffffu, rs, off);
            l_i[i] = l_i[i] * corr + rs;
            #pragma unroll
            for (int j = 0; j < 4; j++) {
                acc[i][j] *= corr;
                Ps[(r0+i)*PSTR + c0 + j] = s[i][j];
            }
        }
        __syncthreads();

        // ---- acc += P @ V ----
        #pragma unroll 4
        for (int c4 = 0; c4 < 16; c4++) {
            float4 p4[4];
            #pragma unroll
            for (int i = 0; i < 4; i++)
                p4[i] = *(const float4*)(Ps + (r0+i)*PSTR + c4*4);
            #pragma unroll
            for (int cc = 0; cc < 4; cc++) {
                const float4 vv = *(const float4*)(Vs + (c4*4+cc)*VSTR + c0);
                const float* vf = (const float*)&vv;
                #pragma unroll
                for (int i = 0; i < 4; i++) {
                    const float p = ((const float*)&p4[i])[cc];
                    #pragma unroll
                    for (int j = 0; j < 4; j++)
                        acc[i][j] = fmaf(p, vf[j], acc[i][j]);
                }
            }
        }
    }

    // ---- epilogue ----
    #pragma unroll
    for (int i = 0; i < 4; i++) {
        const float inv = 1.f / l_i[i];
        float4 o;
        o.x = acc[i][0]*inv; o.y = acc[i][1]*inv;
        o.z = acc[i][2]*inv; o.w = acc[i][3]*inv;
        *(float4*)(out + ((size_t)b*L + lq0 + r0 + i)*HID + h*HS + c0) = o;
    }
}

// ============================================================================
extern "C" void kernel_launch(void* const* d_in, const int* in_sizes, int n_in,
                              void* d_out, int out_size) {
    const float* hs   = (const float*)d_in[0];
    const float* mask = (const float*)d_in[1];
    const float* rel  = (const float*)d_in[2];
    const float* Wq   = (const float*)d_in[3];
    const float* bq   = (const float*)d_in[4];
    const float* Wk   = (const float*)d_in[5];
    const float* Wv   = (const float*)d_in[6];
    const float* bv   = (const float*)d_in[7];
    const float* Wg   = (const float*)d_in[8];
    const float* bg   = (const float*)d_in[9];
    const float* eco  = (const float*)d_in[10];
    float* out = (float*)d_out;

    // projections: Q (N=2048, bias), K (N=2048, no bias), V (N=1024, bias)
    proj_kernel<<<dim3(2048/64, ML/64), 256>>>(hs, Wq, bq,  E,  0);
    proj_kernel<<<dim3(2048/64, ML/64), 256>>>(hs, Wk, nullptr, E, 1);
    proj_kernel<<<dim3(1024/64, ML/64), 256>>>(hs, Wv, bv,  HS, 2);

    // gates
    gate_kernel<<<(B*NH*L)/8, 256>>>(Wg, bg, eco);

    // attention
    const int smem_bytes = (BM*QSTR + BN*QSTR + BN*VSTR + BM*PSTR + BM) * sizeof(float);
    cudaFuncSetAttribute(attn_kernel,
                         cudaFuncAttributeMaxDynamicSharedMemorySize, smem_bytes);
    attn_kernel<<<dim3(L/BM, NH, B), 256, smem_bytes>>>(mask, rel, out);
}